// round 7
// baseline (speedup 1.0000x reference)
#include <cuda_runtime.h>
#include <math.h>
#include <stdint.h>

// Problem constants
#define B_  4
#define N_  2048
#define D_  1024
#define E_  16
#define C_  256
#define BNEC_ (4LL * 2048 * 16 * 256)   // 33,554,432 elements per output tensor
#define FLT_MIN_NORMAL 1.17549435082228750797e-38f  // 2^-126

#define HALF_OFF (B_ * E_ * N_)

// Partial logits: [half][b][e][n] (raw dots, un-scaled; K2 applies /exp(temp))
__device__ float g_plog[2 * B_ * E_ * N_];

// ---------------------------------------------------------------------------
// Kernel 1: half-D partial gate logits. 512 blocks: blockIdx>>8 selects the
// dim half, low 8 bits select the token group (8 warps x 4 tokens). 32KB SMEM
// query tile for this half; key loads software-pipelined (first loads issued
// before the staging sync, next iteration prefetched during FMAs).
// Standalone => own register budget, uncongested read path.
// ---------------------------------------------------------------------------
__global__ __launch_bounds__(256) void logits_kernel(
        const float* __restrict__ key,
        const float* __restrict__ query) {
    __shared__ float sq[E_ * 512];   // 32 KB: 16 experts x 512 dims (this half)

    const int lane = threadIdx.x & 31;
    const int warp = threadIdx.x >> 5;
    const int half = blockIdx.x >> 8;                    // dim half 0/1
    const int tok0 = (((int)blockIdx.x & 255) * 8 + warp) * 4;

    // Prefetch i=0 key vectors BEFORE staging sync.
    const float4* kp[4];
    #pragma unroll
    for (int t = 0; t < 4; ++t)
        kp[t] = reinterpret_cast<const float4*>(
                    key + (long long)(tok0 + t) * D_ + half * 512);
    float4 kv[4], kvn[4];
    #pragma unroll
    for (int t = 0; t < 4; ++t) kv[t] = kp[t][lane];

    // Stage this half of query.
    for (int i = threadIdx.x; i < E_ * 512; i += 256) {
        int e = i >> 9, j = i & 511;
        sq[i] = query[e * D_ + half * 512 + j];
    }
    __syncthreads();

    float acc[4][E_];
    #pragma unroll
    for (int t = 0; t < 4; t++)
        #pragma unroll
        for (int e = 0; e < E_; e++) acc[t][e] = 0.f;

    const float4* sq4 = reinterpret_cast<const float4*>(sq);
    #pragma unroll
    for (int i = 0; i < 4; ++i) {
        if (i < 3) {
            int dvn = lane + 32 * (i + 1);
            #pragma unroll
            for (int t = 0; t < 4; ++t) kvn[t] = kp[t][dvn];
        }
        int dv = lane + 32 * i;
        #pragma unroll
        for (int e = 0; e < E_; ++e) {
            float4 q = sq4[e * 128 + dv];
            #pragma unroll
            for (int t = 0; t < 4; ++t) {
                acc[t][e] += kv[t].x * q.x;
                acc[t][e] += kv[t].y * q.y;
                acc[t][e] += kv[t].z * q.z;
                acc[t][e] += kv[t].w * q.w;
            }
        }
        #pragma unroll
        for (int t = 0; t < 4; ++t) kv[t] = kvn[t];
    }

    #pragma unroll
    for (int t = 0; t < 4; ++t) {
        int tok = tok0 + t;
        int b = tok >> 11, n = tok & (N_ - 1);
        #pragma unroll
        for (int e = 0; e < E_; ++e) {
            float v = acc[t][e];
            #pragma unroll
            for (int off = 16; off > 0; off >>= 1)
                v += __shfl_xor_sync(0xffffffffu, v, off);
            if (lane == 0)
                g_plog[half * HALF_OFF + (b * E_ + e) * N_ + n] = v;
        }
    }
}

// ---------------------------------------------------------------------------
// Kernel 2: per (b,e) row — softmax (ftz on subnormal affinities, matching
// XLA semantics), then SELECT-then-SORT:
//   * nonzero affinities (count m, typically ~50) compact in index order into
//     a 256-slot key array (packed (valbits<<32)|(2047-idx)), bitonic-sorted
//     descending by 128 threads using named barrier 1 -> exact jax top-k
//     order (value desc, index asc);
//   * slots [m,256) are the zero-affinity tokens in ascending index order,
//     written directly from a ballot prefix-scan (dispatch=1.0, combine=0
//     already zeroed by the memset).
// Fallback to a full 2048 bitonic sort if m > 256 (not expected).
// ---------------------------------------------------------------------------
__global__ __launch_bounds__(1024) void topk_scatter_kernel(
        const float* __restrict__ temp,
        float* __restrict__ out, long long out_n) {
    __shared__ unsigned long long sk[N_];   // full array only used in fallback
    __shared__ float red[32];
    __shared__ int scnt[64], sbase[64];
    __shared__ int mTot;

    const int be  = blockIdx.x;           // 0..63
    const int b = be / E_, e = be - b * E_;
    const float* rowA = g_plog + (long long)be * N_;
    const float* rowB = rowA + HALF_OFF;
    const int t = threadIdx.x;
    const int lane = t & 31, w = t >> 5;
    const float et = expf(temp[0]);

    float x0 = (rowA[t] + rowB[t]) / et;
    float x1 = (rowA[t + 1024] + rowB[t + 1024]) / et;

    // ---- block max ----
    float m = fmaxf(x0, x1);
    #pragma unroll
    for (int off = 16; off > 0; off >>= 1)
        m = fmaxf(m, __shfl_xor_sync(0xffffffffu, m, off));
    if (lane == 0) red[w] = m;
    __syncthreads();
    if (t < 32) {
        float v = red[t];
        #pragma unroll
        for (int off = 16; off > 0; off >>= 1)
            v = fmaxf(v, __shfl_xor_sync(0xffffffffu, v, off));
        if (t == 0) red[0] = v;
    }
    __syncthreads();
    m = red[0];
    __syncthreads();

    // ---- exp + sum ----
    float e0 = expf(x0 - m), e1 = expf(x1 - m);
    float s = e0 + e1;
    #pragma unroll
    for (int off = 16; off > 0; off >>= 1)
        s += __shfl_xor_sync(0xffffffffu, s, off);
    if (lane == 0) red[w] = s;
    __syncthreads();
    if (t < 32) {
        float v = red[t];
        #pragma unroll
        for (int off = 16; off > 0; off >>= 1)
            v += __shfl_xor_sync(0xffffffffu, v, off);
        if (t == 0) red[0] = v;
    }
    __syncthreads();
    const float S = red[0];

    // ---- normalize (ftz) ----
    float a0 = e0 / S; if (a0 < FLT_MIN_NORMAL) a0 = 0.f;
    float a1 = e1 / S; if (a1 < FLT_MIN_NORMAL) a1 = 0.f;
    const bool z0 = (a0 == 0.f), z1 = (a1 == 0.f);

    unsigned bal0 = __ballot_sync(0xffffffffu, z0);
    unsigned bal1 = __ballot_sync(0xffffffffu, z1);
    if (lane == 0) { scnt[w] = __popc(bal0); scnt[32 + w] = __popc(bal1); }
    if (t < C_) sk[t] = 0ull;          // pad slots for the 256-sort
    __syncthreads();

    // ---- one-warp exclusive scan over the 64 ordered chunks ----
    if (t < 32) {
        int c0 = scnt[t], c1 = scnt[t + 32];
        int s0 = c0;
        #pragma unroll
        for (int off = 1; off < 32; off <<= 1) {
            int v = __shfl_up_sync(0xffffffffu, s0, off);
            if (t >= off) s0 += v;
        }
        int tot0 = __shfl_sync(0xffffffffu, s0, 31);
        int s1 = c1;
        #pragma unroll
        for (int off = 1; off < 32; off <<= 1) {
            int v = __shfl_up_sync(0xffffffffu, s1, off);
            if (t >= off) s1 += v;
        }
        sbase[t] = s0 - c0;
        sbase[t + 32] = tot0 + s1 - c1;
        if (t == 31) mTot = 2 * 1024 - (tot0 + s1);   // # nonzero affinities
    }
    __syncthreads();
    const int mNZ = mTot;
    const unsigned lmask = (1u << lane) - 1u;
    const int zr0 = sbase[w]      + __popc(bal0 & lmask);   // zeros before idx t
    const int zr1 = sbase[32 + w] + __popc(bal1 & lmask);   // zeros before idx t+1024

    const bool hasC = (out_n >= 2 * BNEC_);

    if (mNZ <= C_) {
        // ---- compact nonzeros (index order; the 256-sort fixes ranking) ----
        if (!z0) {
            int r = t - zr0;
            sk[r] = ((unsigned long long)__float_as_uint(a0) << 32)
                  | (unsigned long long)(2047 - t);
        }
        if (!z1) {
            int r = (t + 1024) - zr1;
            sk[r] = ((unsigned long long)__float_as_uint(a1) << 32)
                  | (unsigned long long)(2047 - (t + 1024));
        }
        // ---- zero-affinity fill: slot c = m + zero_rank (index ascending) ----
        if (z0 && zr0 < C_ - mNZ) {
            long long off = (((long long)b * N_ + t) * E_ + e) * C_ + (mNZ + zr0);
            out[off] = 1.0f;                 // combine = 0, already zeroed
        }
        if (z1 && zr1 < C_ - mNZ) {
            long long off = (((long long)b * N_ + (t + 1024)) * E_ + e) * C_ + (mNZ + zr1);
            out[off] = 1.0f;
        }
        __syncthreads();

        // ---- bitonic sort of 256 keys, descending; warps 0-3 only ----
        if (t < 128) {
            for (int k = 2; k <= 256; k <<= 1) {
                for (int j = k >> 1; j > 0; j >>= 1) {
                    int i = 2 * t - (t & (j - 1));
                    int l = i + j;
                    unsigned long long A = sk[i], Bv = sk[l];
                    bool dir = ((i & k) == 0);
                    bool sw  = dir ? (A < Bv) : (A > Bv);
                    if (sw) { sk[i] = Bv; sk[l] = A; }
                    asm volatile("bar.sync 1, 128;" ::: "memory");
                }
            }
        }
        __syncthreads();

        // ---- scatter sorted nonzeros into slots [0, m) ----
        if (t < mNZ) {
            unsigned long long K = sk[t];
            int   n = 2047 - (int)(K & 0x7FFu);
            float v = __uint_as_float((unsigned int)(K >> 32));
            long long off = (((long long)b * N_ + n) * E_ + e) * C_ + t;
            out[off] = 1.0f;
            if (hasC) out[BNEC_ + off] = v;
        }
    } else {
        // ---- fallback (m > 256): full 2048-key bitonic sort ----
        sk[t]        = ((unsigned long long)__float_as_uint(a0) << 32)
                     | (unsigned long long)(2047 - t);
        sk[t + 1024] = ((unsigned long long)__float_as_uint(a1) << 32)
                     | (unsigned long long)(2047 - (t + 1024));
        __syncthreads();
        for (int k = 2; k <= N_; k <<= 1) {
            for (int j = k >> 1; j > 0; j >>= 1) {
                int i = 2 * t - (t & (j - 1));
                int l = i + j;
                unsigned long long A = sk[i], Bv = sk[l];
                bool dir = ((i & k) == 0);
                bool sw  = dir ? (A < Bv) : (A > Bv);
                if (sw) { sk[i] = Bv; sk[l] = A; }
                __syncthreads();
            }
        }
        if (t < C_) {
            unsigned long long K = sk[t];
            int   n = 2047 - (int)(K & 0x7FFu);
            float v = __uint_as_float((unsigned int)(K >> 32));
            long long off = (((long long)b * N_ + n) * E_ + e) * C_ + t;
            out[off] = 1.0f;
            if (hasC) out[BNEC_ + off] = v;
        }
    }
}

// ---------------------------------------------------------------------------
extern "C" void kernel_launch(void* const* d_in, const int* in_sizes, int n_in,
                              void* d_out, int out_size) {
    const float* key = nullptr; const float* query = nullptr; const float* temp = nullptr;
    for (int i = 0; i < n_in; ++i) {
        if (in_sizes[i] == B_ * N_ * D_)      key   = (const float*)d_in[i];
        else if (in_sizes[i] == E_ * D_)      query = (const float*)d_in[i];
        else if (in_sizes[i] == 1)            temp  = (const float*)d_in[i];
    }
    if (!key)   key   = (const float*)d_in[0];
    if (!query) query = (const float*)d_in[1];
    if (!temp)  temp  = (const float*)d_in[2];
    float* out = (float*)d_out;

    // 1) driver-optimized zero fill of the 268 MB output (graph memset node;
    //    no allocation, async, capturable).
    cudaMemsetAsync(out, 0, (size_t)out_size * sizeof(float));
    // 2) half-D partial logits (own register/SMEM budget, uncongested reads).
    logits_kernel<<<512, 256>>>(key, query);
    // 3) softmax + select-then-sort top-256 + direct scatter.
    topk_scatter_kernel<<<B_ * E_, 1024>>>(temp, out, (long long)out_size);
}

// round 8
// speedup vs baseline: 1.2526x; 1.2526x over previous
#include <cuda_runtime.h>
#include <math.h>
#include <stdint.h>

// Problem constants
#define B_  4
#define N_  2048
#define D_  1024
#define E_  16
#define C_  256
#define BNEC_ (4LL * 2048 * 16 * 256)   // 33,554,432 elements per output tensor
#define FLT_MIN_NORMAL 1.17549435082228750797e-38f  // 2^-126

#define NLOG_BLOCKS 1024         // 2 halves x 512 (2 tokens/warp)
#define NZERO_BLOCKS 4096
#define HALF_OFF (B_ * E_ * N_)

// Partial logits: [half][b][e][n] (raw dots; K2 applies /exp(temp))
__device__ float g_plog[2 * B_ * E_ * N_];

// ---------------------------------------------------------------------------
// Kernel 1 (fused, 64-reg capped): blocks [0,1024) compute half-D partial
// gate logits at 2 tokens/warp (acc[2][16] keeps the path under the cap, so
// the fill blocks get 4 blocks/SM instead of 2); blocks [1024, 5120)
// zero-fill the 268MB output with streaming float4 stores. Logits blocks take
// the LOW block indices so they are resident in wave 1 and hide under the
// DRAM-bound fill.
// ---------------------------------------------------------------------------
__global__ __launch_bounds__(256, 4) void fused_zero_logits_kernel(
        const float* __restrict__ key,
        const float* __restrict__ query,
        float* __restrict__ out, long long out_n) {
    if (blockIdx.x >= NLOG_BLOCKS) {
        // ---------------- zero-fill path ----------------
        long long n4 = out_n >> 2;
        float4* o4 = reinterpret_cast<float4*>(out);
        long long i = (long long)(blockIdx.x - NLOG_BLOCKS) * 256 + threadIdx.x;
        long long stride = (long long)NZERO_BLOCKS * 256;
        float4 z = make_float4(0.f, 0.f, 0.f, 0.f);
        for (long long k = i; k < n4; k += stride) __stcs(&o4[k], z);
        long long tail = n4 << 2;
        if (i < out_n - tail) out[tail + i] = 0.f;
        return;
    }

    // ---------------- logits path (2 tokens per warp) ----------------
    __shared__ float sq[E_ * 512];   // 32 KB: 16 experts x 512 dims (this half)

    const int lane = threadIdx.x & 31;
    const int warp = threadIdx.x >> 5;
    const int half = blockIdx.x >> 9;                     // dim half 0/1
    const int tok0 = (((int)blockIdx.x & 511) * 8 + warp) * 2;

    // Prefetch i=0 key vectors BEFORE the staging sync.
    const float4* kp[2];
    #pragma unroll
    for (int t = 0; t < 2; ++t)
        kp[t] = reinterpret_cast<const float4*>(
                    key + (long long)(tok0 + t) * D_ + half * 512);
    float4 kv[2], kvn[2];
    #pragma unroll
    for (int t = 0; t < 2; ++t) kv[t] = kp[t][lane];

    // Stage this half of query.
    for (int i = threadIdx.x; i < E_ * 512; i += 256) {
        int e = i >> 9, j = i & 511;
        sq[i] = query[e * D_ + half * 512 + j];
    }
    __syncthreads();

    float acc[2][E_];
    #pragma unroll
    for (int t = 0; t < 2; t++)
        #pragma unroll
        for (int e = 0; e < E_; e++) acc[t][e] = 0.f;

    const float4* sq4 = reinterpret_cast<const float4*>(sq);
    #pragma unroll
    for (int i = 0; i < 4; ++i) {
        if (i < 3) {
            int dvn = lane + 32 * (i + 1);
            #pragma unroll
            for (int t = 0; t < 2; ++t) kvn[t] = kp[t][dvn];
        }
        int dv = lane + 32 * i;
        #pragma unroll
        for (int e = 0; e < E_; ++e) {
            float4 q = sq4[e * 128 + dv];
            #pragma unroll
            for (int t = 0; t < 2; ++t) {
                acc[t][e] += kv[t].x * q.x;
                acc[t][e] += kv[t].y * q.y;
                acc[t][e] += kv[t].z * q.z;
                acc[t][e] += kv[t].w * q.w;
            }
        }
        #pragma unroll
        for (int t = 0; t < 2; ++t) kv[t] = kvn[t];
    }

    #pragma unroll
    for (int t = 0; t < 2; ++t) {
        int tok = tok0 + t;
        int b = tok >> 11, n = tok & (N_ - 1);
        #pragma unroll
        for (int e = 0; e < E_; ++e) {
            float v = acc[t][e];
            #pragma unroll
            for (int off = 16; off > 0; off >>= 1)
                v += __shfl_xor_sync(0xffffffffu, v, off);
            if (lane == 0)
                g_plog[half * HALF_OFF + (b * E_ + e) * N_ + n] = v;
        }
    }
}

// ---------------------------------------------------------------------------
// Kernel 2: per (b,e) row — softmax (ftz on subnormal affinities, matching
// XLA semantics), then SELECT-then-SORT:
//   * nonzero affinities (count m, typically ~50) compact in index order into
//     a 256-slot key array (packed (valbits<<32)|(2047-idx)), bitonic-sorted
//     descending by 128 threads using named barrier 1 -> exact jax top-k
//     order (value desc, index asc);
//   * slots [m,256) are zero-affinity tokens in ascending index order, written
//     directly from a ballot prefix-scan (dispatch=1.0, combine=0 already).
// Fallback to a full 2048 bitonic sort if m > 256 (not expected).
// ---------------------------------------------------------------------------
__global__ __launch_bounds__(1024) void topk_scatter_kernel(
        const float* __restrict__ temp,
        float* __restrict__ out, long long out_n) {
    __shared__ unsigned long long sk[N_];   // full array only used in fallback
    __shared__ float red[32];
    __shared__ int scnt[64], sbase[64];
    __shared__ int mTot;

    const int be  = blockIdx.x;           // 0..63
    const int b = be / E_, e = be - b * E_;
    const float* rowA = g_plog + (long long)be * N_;
    const float* rowB = rowA + HALF_OFF;
    const int t = threadIdx.x;
    const int lane = t & 31, w = t >> 5;
    const float et = expf(temp[0]);

    float x0 = (rowA[t] + rowB[t]) / et;
    float x1 = (rowA[t + 1024] + rowB[t + 1024]) / et;

    // ---- block max ----
    float m = fmaxf(x0, x1);
    #pragma unroll
    for (int off = 16; off > 0; off >>= 1)
        m = fmaxf(m, __shfl_xor_sync(0xffffffffu, m, off));
    if (lane == 0) red[w] = m;
    __syncthreads();
    if (t < 32) {
        float v = red[t];
        #pragma unroll
        for (int off = 16; off > 0; off >>= 1)
            v = fmaxf(v, __shfl_xor_sync(0xffffffffu, v, off));
        if (t == 0) red[0] = v;
    }
    __syncthreads();
    m = red[0];
    __syncthreads();

    // ---- exp + sum ----
    float e0 = expf(x0 - m), e1 = expf(x1 - m);
    float s = e0 + e1;
    #pragma unroll
    for (int off = 16; off > 0; off >>= 1)
        s += __shfl_xor_sync(0xffffffffu, s, off);
    if (lane == 0) red[w] = s;
    __syncthreads();
    if (t < 32) {
        float v = red[t];
        #pragma unroll
        for (int off = 16; off > 0; off >>= 1)
            v += __shfl_xor_sync(0xffffffffu, v, off);
        if (t == 0) red[0] = v;
    }
    __syncthreads();
    const float S = red[0];

    // ---- normalize (ftz) ----
    float a0 = e0 / S; if (a0 < FLT_MIN_NORMAL) a0 = 0.f;
    float a1 = e1 / S; if (a1 < FLT_MIN_NORMAL) a1 = 0.f;
    const bool z0 = (a0 == 0.f), z1 = (a1 == 0.f);

    unsigned bal0 = __ballot_sync(0xffffffffu, z0);
    unsigned bal1 = __ballot_sync(0xffffffffu, z1);
    if (lane == 0) { scnt[w] = __popc(bal0); scnt[32 + w] = __popc(bal1); }
    if (t < C_) sk[t] = 0ull;          // pad slots for the 256-sort
    __syncthreads();

    // ---- one-warp exclusive scan over the 64 ordered chunks ----
    if (t < 32) {
        int c0 = scnt[t], c1 = scnt[t + 32];
        int s0 = c0;
        #pragma unroll
        for (int off = 1; off < 32; off <<= 1) {
            int v = __shfl_up_sync(0xffffffffu, s0, off);
            if (t >= off) s0 += v;
        }
        int tot0 = __shfl_sync(0xffffffffu, s0, 31);
        int s1 = c1;
        #pragma unroll
        for (int off = 1; off < 32; off <<= 1) {
            int v = __shfl_up_sync(0xffffffffu, s1, off);
            if (t >= off) s1 += v;
        }
        sbase[t] = s0 - c0;
        sbase[t + 32] = tot0 + s1 - c1;
        if (t == 31) mTot = 2 * 1024 - (tot0 + s1);   // # nonzero affinities
    }
    __syncthreads();
    const int mNZ = mTot;
    const unsigned lmask = (1u << lane) - 1u;
    const int zr0 = sbase[w]      + __popc(bal0 & lmask);   // zeros before idx t
    const int zr1 = sbase[32 + w] + __popc(bal1 & lmask);   // zeros before idx t+1024

    const bool hasC = (out_n >= 2 * BNEC_);

    if (mNZ <= C_) {
        // ---- compact nonzeros (index order; the 256-sort fixes ranking) ----
        if (!z0) {
            int r = t - zr0;
            sk[r] = ((unsigned long long)__float_as_uint(a0) << 32)
                  | (unsigned long long)(2047 - t);
        }
        if (!z1) {
            int r = (t + 1024) - zr1;
            sk[r] = ((unsigned long long)__float_as_uint(a1) << 32)
                  | (unsigned long long)(2047 - (t + 1024));
        }
        // ---- zero-affinity fill: slot c = m + zero_rank (index ascending) ----
        if (z0 && zr0 < C_ - mNZ) {
            long long off = (((long long)b * N_ + t) * E_ + e) * C_ + (mNZ + zr0);
            out[off] = 1.0f;                 // combine = 0, already zeroed
        }
        if (z1 && zr1 < C_ - mNZ) {
            long long off = (((long long)b * N_ + (t + 1024)) * E_ + e) * C_ + (mNZ + zr1);
            out[off] = 1.0f;
        }
        __syncthreads();

        // ---- bitonic sort of 256 keys, descending; warps 0-3 only ----
        if (t < 128) {
            for (int k = 2; k <= 256; k <<= 1) {
                for (int j = k >> 1; j > 0; j >>= 1) {
                    int i = 2 * t - (t & (j - 1));
                    int l = i + j;
                    unsigned long long A = sk[i], Bv = sk[l];
                    bool dir = ((i & k) == 0);
                    bool sw  = dir ? (A < Bv) : (A > Bv);
                    if (sw) { sk[i] = Bv; sk[l] = A; }
                    asm volatile("bar.sync 1, 128;" ::: "memory");
                }
            }
        }
        __syncthreads();

        // ---- scatter sorted nonzeros into slots [0, m) ----
        if (t < mNZ) {
            unsigned long long K = sk[t];
            int   n = 2047 - (int)(K & 0x7FFu);
            float v = __uint_as_float((unsigned int)(K >> 32));
            long long off = (((long long)b * N_ + n) * E_ + e) * C_ + t;
            out[off] = 1.0f;
            if (hasC) out[BNEC_ + off] = v;
        }
    } else {
        // ---- fallback (m > 256): full 2048-key bitonic sort ----
        sk[t]        = ((unsigned long long)__float_as_uint(a0) << 32)
                     | (unsigned long long)(2047 - t);
        sk[t + 1024] = ((unsigned long long)__float_as_uint(a1) << 32)
                     | (unsigned long long)(2047 - (t + 1024));
        __syncthreads();
        for (int k = 2; k <= N_; k <<= 1) {
            for (int j = k >> 1; j > 0; j >>= 1) {
                int i = 2 * t - (t & (j - 1));
                int l = i + j;
                unsigned long long A = sk[i], Bv = sk[l];
                bool dir = ((i & k) == 0);
                bool sw  = dir ? (A < Bv) : (A > Bv);
                if (sw) { sk[i] = Bv; sk[l] = A; }
                __syncthreads();
            }
        }
        if (t < C_) {
            unsigned long long K = sk[t];
            int   n = 2047 - (int)(K & 0x7FFu);
            float v = __uint_as_float((unsigned int)(K >> 32));
            long long off = (((long long)b * N_ + n) * E_ + e) * C_ + t;
            out[off] = 1.0f;
            if (hasC) out[BNEC_ + off] = v;
        }
    }
}

// ---------------------------------------------------------------------------
extern "C" void kernel_launch(void* const* d_in, const int* in_sizes, int n_in,
                              void* d_out, int out_size) {
    const float* key = nullptr; const float* query = nullptr; const float* temp = nullptr;
    for (int i = 0; i < n_in; ++i) {
        if (in_sizes[i] == B_ * N_ * D_)      key   = (const float*)d_in[i];
        else if (in_sizes[i] == E_ * D_)      query = (const float*)d_in[i];
        else if (in_sizes[i] == 1)            temp  = (const float*)d_in[i];
    }
    if (!key)   key   = (const float*)d_in[0];
    if (!query) query = (const float*)d_in[1];
    if (!temp)  temp  = (const float*)d_in[2];
    float* out = (float*)d_out;

    // K1: zero-fill (268 MB, DRAM-bound) + 64-reg-capped logits overlapped.
    fused_zero_logits_kernel<<<NLOG_BLOCKS + NZERO_BLOCKS, 256>>>(
        key, query, out, (long long)out_size);
    // K2: softmax + select-then-sort top-256 + direct scatter.
    topk_scatter_kernel<<<B_ * E_, 1024>>>(temp, out, (long long)out_size);
}

// round 9
// speedup vs baseline: 1.3151x; 1.0499x over previous
#include <cuda_runtime.h>
#include <math.h>
#include <stdint.h>

// Problem constants
#define B_  4
#define N_  2048
#define D_  1024
#define E_  16
#define C_  256
#define BNEC_ (4LL * 2048 * 16 * 256)   // 33,554,432 elements per output tensor
#define FLT_MIN_NORMAL 1.17549435082228750797e-38f  // 2^-126

#define NLOG_BLOCKS 1024         // 2 halves x 512 (2 tokens/warp)
#define NZERO_BLOCKS 4096
#define NTOT_BLOCKS (NLOG_BLOCKS + NZERO_BLOCKS)
#define HALF_OFF (B_ * E_ * N_)

// Partial logits: [half][b][e][n] (raw dots; K2 applies /exp(temp))
__device__ float g_plog[2 * B_ * E_ * N_];

// ---------------------------------------------------------------------------
// Kernel 1 (fused, 64-reg capped, INTERLEAVED roles): among blocks [0,4096),
// every 4th block (idx%4==0) is a logits block (1024 total; logits-id =
// idx>>2) and the rest are fill blocks; blocks [4096,5120) are extra fill
// blocks. This puts ~1 logits block per 3 fill blocks in EVERY wave, so the
// FFMA/LDS-bound logits work hides under the DRAM-store-bound fill instead of
// running in logits-only leading waves (the round-8 mistake).
// ---------------------------------------------------------------------------
__global__ __launch_bounds__(256, 4) void fused_zero_logits_kernel(
        const float* __restrict__ key,
        const float* __restrict__ query,
        float* __restrict__ out, long long out_n) {
    const int bx = blockIdx.x;
    const bool is_logits = (bx < 4096) && ((bx & 3) == 0);

    if (!is_logits) {
        // ---------------- zero-fill path ----------------
        // Contiguous fill ids: first 4096 blocks contribute 3 of every 4.
        int fid = (bx < 4096) ? (3 * (bx >> 2) + (bx & 3) - 1)
                              : (3072 + (bx - 4096));
        long long n4 = out_n >> 2;
        float4* o4 = reinterpret_cast<float4*>(out);
        long long i = (long long)fid * 256 + threadIdx.x;
        long long stride = (long long)NZERO_BLOCKS * 256;
        float4 z = make_float4(0.f, 0.f, 0.f, 0.f);
        for (long long k = i; k < n4; k += stride) __stcs(&o4[k], z);
        long long tail = n4 << 2;
        if (i < out_n - tail) out[tail + i] = 0.f;
        return;
    }

    // ---------------- logits path (2 tokens per warp) ----------------
    const int lid_blk = bx >> 2;                          // 0..1023
    __shared__ float sq[E_ * 512];   // 32 KB: 16 experts x 512 dims (this half)

    const int lane = threadIdx.x & 31;
    const int warp = threadIdx.x >> 5;
    const int half = lid_blk >> 9;                        // dim half 0/1
    const int tok0 = ((lid_blk & 511) * 8 + warp) * 2;

    // Prefetch i=0 key vectors BEFORE the staging sync.
    const float4* kp[2];
    #pragma unroll
    for (int t = 0; t < 2; ++t)
        kp[t] = reinterpret_cast<const float4*>(
                    key + (long long)(tok0 + t) * D_ + half * 512);
    float4 kv[2], kvn[2];
    #pragma unroll
    for (int t = 0; t < 2; ++t) kv[t] = kp[t][lane];

    // Stage this half of query.
    for (int i = threadIdx.x; i < E_ * 512; i += 256) {
        int e = i >> 9, j = i & 511;
        sq[i] = query[e * D_ + half * 512 + j];
    }
    __syncthreads();

    float acc[2][E_];
    #pragma unroll
    for (int t = 0; t < 2; t++)
        #pragma unroll
        for (int e = 0; e < E_; e++) acc[t][e] = 0.f;

    const float4* sq4 = reinterpret_cast<const float4*>(sq);
    #pragma unroll
    for (int i = 0; i < 4; ++i) {
        if (i < 3) {
            int dvn = lane + 32 * (i + 1);
            #pragma unroll
            for (int t = 0; t < 2; ++t) kvn[t] = kp[t][dvn];
        }
        int dv = lane + 32 * i;
        #pragma unroll
        for (int e = 0; e < E_; ++e) {
            float4 q = sq4[e * 128 + dv];
            #pragma unroll
            for (int t = 0; t < 2; ++t) {
                acc[t][e] += kv[t].x * q.x;
                acc[t][e] += kv[t].y * q.y;
                acc[t][e] += kv[t].z * q.z;
                acc[t][e] += kv[t].w * q.w;
            }
        }
        #pragma unroll
        for (int t = 0; t < 2; ++t) kv[t] = kvn[t];
    }

    #pragma unroll
    for (int t = 0; t < 2; ++t) {
        int tok = tok0 + t;
        int b = tok >> 11, n = tok & (N_ - 1);
        #pragma unroll
        for (int e = 0; e < E_; ++e) {
            float v = acc[t][e];
            #pragma unroll
            for (int off = 16; off > 0; off >>= 1)
                v += __shfl_xor_sync(0xffffffffu, v, off);
            if (lane == 0)
                g_plog[half * HALF_OFF + (b * E_ + e) * N_ + n] = v;
        }
    }
}

// ---------------------------------------------------------------------------
// Kernel 2: per (b,e) row — softmax (ftz on subnormal affinities, matching
// XLA semantics), then SELECT-then-SORT:
//   * nonzero affinities (count m, typically ~50) compact in index order into
//     a 256-slot key array (packed (valbits<<32)|(2047-idx)), bitonic-sorted
//     descending by 128 threads using named barrier 1 -> exact jax top-k
//     order (value desc, index asc);
//   * slots [m,256) are zero-affinity tokens in ascending index order, written
//     directly from a ballot prefix-scan (dispatch=1.0, combine=0 already).
// Fallback to a full 2048 bitonic sort if m > 256 (not expected).
// ---------------------------------------------------------------------------
__global__ __launch_bounds__(1024) void topk_scatter_kernel(
        const float* __restrict__ temp,
        float* __restrict__ out, long long out_n) {
    __shared__ unsigned long long sk[N_];   // full array only used in fallback
    __shared__ float red[32];
    __shared__ int scnt[64], sbase[64];
    __shared__ int mTot;

    const int be  = blockIdx.x;           // 0..63
    const int b = be / E_, e = be - b * E_;
    const float* rowA = g_plog + (long long)be * N_;
    const float* rowB = rowA + HALF_OFF;
    const int t = threadIdx.x;
    const int lane = t & 31, w = t >> 5;
    const float et = expf(temp[0]);

    float x0 = (rowA[t] + rowB[t]) / et;
    float x1 = (rowA[t + 1024] + rowB[t + 1024]) / et;

    // ---- block max ----
    float m = fmaxf(x0, x1);
    #pragma unroll
    for (int off = 16; off > 0; off >>= 1)
        m = fmaxf(m, __shfl_xor_sync(0xffffffffu, m, off));
    if (lane == 0) red[w] = m;
    __syncthreads();
    if (t < 32) {
        float v = red[t];
        #pragma unroll
        for (int off = 16; off > 0; off >>= 1)
            v = fmaxf(v, __shfl_xor_sync(0xffffffffu, v, off));
        if (t == 0) red[0] = v;
    }
    __syncthreads();
    m = red[0];
    __syncthreads();

    // ---- exp + sum ----
    float e0 = expf(x0 - m), e1 = expf(x1 - m);
    float s = e0 + e1;
    #pragma unroll
    for (int off = 16; off > 0; off >>= 1)
        s += __shfl_xor_sync(0xffffffffu, s, off);
    if (lane == 0) red[w] = s;
    __syncthreads();
    if (t < 32) {
        float v = red[t];
        #pragma unroll
        for (int off = 16; off > 0; off >>= 1)
            v += __shfl_xor_sync(0xffffffffu, v, off);
        if (t == 0) red[0] = v;
    }
    __syncthreads();
    const float S = red[0];

    // ---- normalize (ftz) ----
    float a0 = e0 / S; if (a0 < FLT_MIN_NORMAL) a0 = 0.f;
    float a1 = e1 / S; if (a1 < FLT_MIN_NORMAL) a1 = 0.f;
    const bool z0 = (a0 == 0.f), z1 = (a1 == 0.f);

    unsigned bal0 = __ballot_sync(0xffffffffu, z0);
    unsigned bal1 = __ballot_sync(0xffffffffu, z1);
    if (lane == 0) { scnt[w] = __popc(bal0); scnt[32 + w] = __popc(bal1); }
    if (t < C_) sk[t] = 0ull;          // pad slots for the 256-sort
    __syncthreads();

    // ---- one-warp exclusive scan over the 64 ordered chunks ----
    if (t < 32) {
        int c0 = scnt[t], c1 = scnt[t + 32];
        int s0 = c0;
        #pragma unroll
        for (int off = 1; off < 32; off <<= 1) {
            int v = __shfl_up_sync(0xffffffffu, s0, off);
            if (t >= off) s0 += v;
        }
        int tot0 = __shfl_sync(0xffffffffu, s0, 31);
        int s1 = c1;
        #pragma unroll
        for (int off = 1; off < 32; off <<= 1) {
            int v = __shfl_up_sync(0xffffffffu, s1, off);
            if (t >= off) s1 += v;
        }
        sbase[t] = s0 - c0;
        sbase[t + 32] = tot0 + s1 - c1;
        if (t == 31) mTot = 2 * 1024 - (tot0 + s1);   // # nonzero affinities
    }
    __syncthreads();
    const int mNZ = mTot;
    const unsigned lmask = (1u << lane) - 1u;
    const int zr0 = sbase[w]      + __popc(bal0 & lmask);   // zeros before idx t
    const int zr1 = sbase[32 + w] + __popc(bal1 & lmask);   // zeros before idx t+1024

    const bool hasC = (out_n >= 2 * BNEC_);

    if (mNZ <= C_) {
        // ---- compact nonzeros (index order; the 256-sort fixes ranking) ----
        if (!z0) {
            int r = t - zr0;
            sk[r] = ((unsigned long long)__float_as_uint(a0) << 32)
                  | (unsigned long long)(2047 - t);
        }
        if (!z1) {
            int r = (t + 1024) - zr1;
            sk[r] = ((unsigned long long)__float_as_uint(a1) << 32)
                  | (unsigned long long)(2047 - (t + 1024));
        }
        // ---- zero-affinity fill: slot c = m + zero_rank (index ascending) ----
        if (z0 && zr0 < C_ - mNZ) {
            long long off = (((long long)b * N_ + t) * E_ + e) * C_ + (mNZ + zr0);
            out[off] = 1.0f;                 // combine = 0, already zeroed
        }
        if (z1 && zr1 < C_ - mNZ) {
            long long off = (((long long)b * N_ + (t + 1024)) * E_ + e) * C_ + (mNZ + zr1);
            out[off] = 1.0f;
        }
        __syncthreads();

        // ---- bitonic sort of 256 keys, descending; warps 0-3 only ----
        if (t < 128) {
            for (int k = 2; k <= 256; k <<= 1) {
                for (int j = k >> 1; j > 0; j >>= 1) {
                    int i = 2 * t - (t & (j - 1));
                    int l = i + j;
                    unsigned long long A = sk[i], Bv = sk[l];
                    bool dir = ((i & k) == 0);
                    bool sw  = dir ? (A < Bv) : (A > Bv);
                    if (sw) { sk[i] = Bv; sk[l] = A; }
                    asm volatile("bar.sync 1, 128;" ::: "memory");
                }
            }
        }
        __syncthreads();

        // ---- scatter sorted nonzeros into slots [0, m) ----
        if (t < mNZ) {
            unsigned long long K = sk[t];
            int   n = 2047 - (int)(K & 0x7FFu);
            float v = __uint_as_float((unsigned int)(K >> 32));
            long long off = (((long long)b * N_ + n) * E_ + e) * C_ + t;
            out[off] = 1.0f;
            if (hasC) out[BNEC_ + off] = v;
        }
    } else {
        // ---- fallback (m > 256): full 2048-key bitonic sort ----
        sk[t]        = ((unsigned long long)__float_as_uint(a0) << 32)
                     | (unsigned long long)(2047 - t);
        sk[t + 1024] = ((unsigned long long)__float_as_uint(a1) << 32)
                     | (unsigned long long)(2047 - (t + 1024));
        __syncthreads();
        for (int k = 2; k <= N_; k <<= 1) {
            for (int j = k >> 1; j > 0; j >>= 1) {
                int i = 2 * t - (t & (j - 1));
                int l = i + j;
                unsigned long long A = sk[i], Bv = sk[l];
                bool dir = ((i & k) == 0);
                bool sw  = dir ? (A < Bv) : (A > Bv);
                if (sw) { sk[i] = Bv; sk[l] = A; }
                __syncthreads();
            }
        }
        if (t < C_) {
            unsigned long long K = sk[t];
            int   n = 2047 - (int)(K & 0x7FFu);
            float v = __uint_as_float((unsigned int)(K >> 32));
            long long off = (((long long)b * N_ + n) * E_ + e) * C_ + t;
            out[off] = 1.0f;
            if (hasC) out[BNEC_ + off] = v;
        }
    }
}

// ---------------------------------------------------------------------------
extern "C" void kernel_launch(void* const* d_in, const int* in_sizes, int n_in,
                              void* d_out, int out_size) {
    const float* key = nullptr; const float* query = nullptr; const float* temp = nullptr;
    for (int i = 0; i < n_in; ++i) {
        if (in_sizes[i] == B_ * N_ * D_)      key   = (const float*)d_in[i];
        else if (in_sizes[i] == E_ * D_)      query = (const float*)d_in[i];
        else if (in_sizes[i] == 1)            temp  = (const float*)d_in[i];
    }
    if (!key)   key   = (const float*)d_in[0];
    if (!query) query = (const float*)d_in[1];
    if (!temp)  temp  = (const float*)d_in[2];
    float* out = (float*)d_out;

    // K1: zero-fill (268 MB, DRAM-bound) + interleaved 64-reg-capped logits.
    fused_zero_logits_kernel<<<NTOT_BLOCKS, 256>>>(
        key, query, out, (long long)out_size);
    // K2: softmax + select-then-sort top-256 + direct scatter.
    topk_scatter_kernel<<<B_ * E_, 1024>>>(temp, out, (long long)out_size);
}